// round 1
// baseline (speedup 1.0000x reference)
#include <cuda_runtime.h>
#include <math.h>

#define N_BOX 256
#define M_PTS 512

// Scratch (device globals; no allocations allowed)
__device__ float4 g_KD[N_BOX * M_PTS];   // per-(i,k): mx, my, P_k, u_k
__device__ float  g_KV[N_BOX * M_PTS];   // per-(i,k): v_k
__device__ float4 g_JD[N_BOX * M_PTS];   // per-(i,j): Gx, Gy, grad_x, grad_y
__device__ float  g_partials[2 * N_BOX]; // one per main-kernel block

// c2 = log2(e) / (2 * THETA2^2), THETA2 = 400
#define C2 (1.44269504088896340736f / 320000.0f)

__device__ __forceinline__ float ex2(float x) {
    float y;
    asm("ex2.approx.f32 %0, %1;" : "=f"(y) : "f"(x));
    return y;
}

// ---------------------------------------------------------------------------
// Stage 1: per-(i,k) prep.  Computes approxi_1, Gaussian centers, and the
// restructured per-k / per-j coefficient arrays.
// ---------------------------------------------------------------------------
__global__ void __launch_bounds__(256) prep_kernel(
    const float* __restrict__ pred,
    const float* __restrict__ target,
    const float* __restrict__ mask,
    const float* __restrict__ grad_x,
    const float* __restrict__ grad_y,
    const float* __restrict__ offset)
{
    int idx = blockIdx.x * blockDim.x + threadIdx.x;   // idx = i*512 + k
    if (idx >= N_BOX * M_PTS) return;
    int i = idx >> 9;

    float off0 = offset[2 * i], off1 = offset[2 * i + 1];
    float px = pred[5 * i]     - off0;
    float py = pred[5 * i + 1] - off1;
    float pw = pred[5 * i + 2];
    float ph = pred[5 * i + 3];
    float pa = pred[5 * i + 4];
    float gx = target[5 * i]     - off0;
    float gy = target[5 * i + 1] - off1;
    float gw = target[5 * i + 2];
    float gh = target[5 * i + 3];
    float ga = target[5 * i + 4];

    float mx = mask[2 * idx], my = mask[2 * idx + 1];

    float dx = mx - gx, dy = my - gy;
    float d  = sqrtf(dx * dx + dy * dy);
    float arg = (gx - mx) / d;
    arg = fminf(1.0f, fmaxf(-1.0f, arg));
    float acosv = acosf(arg);
    float beta  = (gy >= my) ? (ga + acosv) : (ga - acosv);

    float cb = cosf(beta), sb = sinf(beta);
    float d_w = fabsf(d * cb);
    float d_h = fabsf(d * sb);

    // (1 - sigmoid(x)) = 1 / (1 + exp(x))
    float s1 = 1.0f / (1.0f + expf(15.0f * (d_w - gw) / gw));
    float s2 = 1.0f / (1.0f + expf(15.0f * (d_h - gh) / gh));
    float a1 = s1 * s2;

    float dwp = pw * d_w / gw;
    float dhp = ph * d_h / gh;
    float cpa = cosf(pa), spa = sinf(pa);
    float wx = dwp * cpa, wy = dwp * spa;
    float hx = -dhp * spa, hy = dhp * cpa;

    const float HPI = 1.57079632679489662f;
    const float PI_ = 3.14159265358979323846f;
    float gpx, gpy;
    if (beta > -HPI && beta <= 0.0f) {          // q2 -> pts[2],[3]
        gpx =  wx - hx;  gpy =  wy - hy;
    } else if (beta > -PI_ && beta <= -HPI) {   // q3 -> pts[4],[5]
        gpx =  wx + hx;  gpy =  wy + hy;
    } else if (beta > HPI && beta <= PI_) {     // q4 -> pts[6],[7]
        gpx = -wx + hx;  gpy = -wy + hy;
    } else {                                    // else -> pts[0],[1]
        gpx = -wx - hx;  gpy = -wy - hy;
    }

    float Gx = px + gpx;
    float Gy = py + gpy;

    float gxv = grad_x[idx];
    float gyv = grad_y[idx];

    g_KD[idx] = make_float4(mx, my, C2 * (mx * mx + my * my), a1 * gxv);
    g_KV[idx] = a1 * gyv;
    g_JD[idx] = make_float4(Gx, Gy, gxv, gyv);
}

// ---------------------------------------------------------------------------
// Stage 2: the 67M-element core.
// Block = (box i, j-half). 256 threads, each handles one j, loops over all k.
// t = Q_j + P_k - a_j*mx_k - b_j*my_k ;  e = 2^t
// A += e*u_k ; B += e*v_k ; partial_j = gx_j*A + gy_j*B
// ---------------------------------------------------------------------------
__global__ void __launch_bounds__(256) main_kernel()
{
    __shared__ float4 sKD[M_PTS];
    __shared__ float  sKV[M_PTS];
    __shared__ float  sWarp[8];

    int i    = blockIdx.x >> 1;
    int half = blockIdx.x & 1;
    int tid  = threadIdx.x;
    int base = i * M_PTS;

    sKD[tid]       = g_KD[base + tid];
    sKD[tid + 256] = g_KD[base + tid + 256];
    sKV[tid]       = g_KV[base + tid];
    sKV[tid + 256] = g_KV[base + tid + 256];
    __syncthreads();

    int j = half * 256 + tid;
    float4 jd = g_JD[base + j];
    float a = 2.0f * C2 * jd.x;
    float b = 2.0f * C2 * jd.y;
    float Q = C2 * (jd.x * jd.x + jd.y * jd.y);

    float A = 0.0f, B = 0.0f;
#pragma unroll 8
    for (int k = 0; k < M_PTS; ++k) {
        float4 kd = sKD[k];
        float t = fmaf(-a, kd.x, kd.z);
        t = fmaf(-b, kd.y, t) + Q;
        float e = ex2(t);
        A = fmaf(e, kd.w, A);
        B = fmaf(e, sKV[k], B);
    }

    float partial = jd.z * A + jd.w * B;

    // deterministic block reduction
#pragma unroll
    for (int o = 16; o > 0; o >>= 1)
        partial += __shfl_down_sync(0xffffffffu, partial, o);
    if ((tid & 31) == 0) sWarp[tid >> 5] = partial;
    __syncthreads();
    if (tid < 8) {
        float s = sWarp[tid];
#pragma unroll
        for (int o = 4; o > 0; o >>= 1)
            s += __shfl_down_sync(0xffu, s, o);
        if (tid == 0) g_partials[blockIdx.x] = s;
    }
}

// ---------------------------------------------------------------------------
// Stage 3: final reduce + scale. 1 block, 512 threads.
// scale = LOSS_WEIGHT / (N * M * M * 2*pi*THETA2)
// ---------------------------------------------------------------------------
__global__ void __launch_bounds__(512) reduce_kernel(float* __restrict__ out)
{
    __shared__ float sWarp[16];
    int tid = threadIdx.x;
    float s = g_partials[tid];
#pragma unroll
    for (int o = 16; o > 0; o >>= 1)
        s += __shfl_down_sync(0xffffffffu, s, o);
    if ((tid & 31) == 0) sWarp[tid >> 5] = s;
    __syncthreads();
    if (tid < 16) {
        float v = sWarp[tid];
#pragma unroll
        for (int o = 8; o > 0; o >>= 1)
            v += __shfl_down_sync(0xffffu, v, o);
        if (tid == 0) {
            double scale = 1.0 / ((double)N_BOX * (double)M_PTS * (double)M_PTS *
                                  2.0 * 3.14159265358979323846 * 400.0);
            *out = (float)((double)v * scale);
        }
    }
}

// ---------------------------------------------------------------------------
extern "C" void kernel_launch(void* const* d_in, const int* in_sizes, int n_in,
                              void* d_out, int out_size)
{
    const float* pred    = (const float*)d_in[0];
    const float* target  = (const float*)d_in[1];
    const float* mask    = (const float*)d_in[2];
    const float* grad_x  = (const float*)d_in[3];
    const float* grad_y  = (const float*)d_in[4];
    const float* offset  = (const float*)d_in[5];
    float* out = (float*)d_out;

    prep_kernel<<<(N_BOX * M_PTS + 255) / 256, 256>>>(pred, target, mask,
                                                      grad_x, grad_y, offset);
    main_kernel<<<2 * N_BOX, 256>>>();
    reduce_kernel<<<1, 512>>>(out);
}

// round 2
// speedup vs baseline: 1.1841x; 1.1841x over previous
#include <cuda_runtime.h>
#include <math.h>

#define N_BOX 256
#define M_PTS 512

// c2 = log2(e) / (2 * THETA2^2), THETA2 = 400
#define C2  (1.44269504088896340736f / 320000.0f)
#define L2E 1.44269504088896340736f

__device__ float g_partials[N_BOX];

typedef unsigned long long ull;

__device__ __forceinline__ ull pk(float lo, float hi) {
    ull r; asm("mov.b64 %0, {%1, %2};" : "=l"(r) : "f"(lo), "f"(hi)); return r;
}
__device__ __forceinline__ void upk(float& lo, float& hi, ull v) {
    asm("mov.b64 {%0, %1}, %2;" : "=f"(lo), "=f"(hi) : "l"(v));
}
__device__ __forceinline__ ull fma2(ull a, ull b, ull c) {
    ull d; asm("fma.rn.f32x2 %0, %1, %2, %3;" : "=l"(d) : "l"(a), "l"(b), "l"(c)); return d;
}
__device__ __forceinline__ ull add2(ull a, ull b) {
    ull d; asm("add.rn.f32x2 %0, %1, %2;" : "=l"(d) : "l"(a), "l"(b)); return d;
}
// packed exp2: two scalar ex2 on the halves of a 64-bit pair
__device__ __forceinline__ ull ex2p(ull t) {
    ull e;
    asm("{ .reg .f32 lo, hi, el, eh;\n\t"
        "  mov.b64 {lo, hi}, %1;\n\t"
        "  ex2.approx.f32 el, lo;\n\t"
        "  ex2.approx.f32 eh, hi;\n\t"
        "  mov.b64 %0, {el, eh}; }"
        : "=l"(e) : "l"(t));
    return e;
}
__device__ __forceinline__ float ex2s(float x) {
    float y; asm("ex2.approx.f32 %0, %1;" : "=f"(y) : "f"(x)); return y;
}

// ---------------------------------------------------------------------------
// Fused kernel: one block per box. Phase 1: per-m prep (m = 0..511) into
// packed smem (k-side) and registers (j-side). Phase 2: 512x512 core with
// f32x2-packed math, 2 j per thread. Deterministic block reduction.
//
// smem packed layout (pair = (m, m+1)):
//   sXY[m/2] = (mx0, mx1, my0, my1)
//   sPU[m/2] = (P0,  P1,  u0,  u1 )   P = C2*(mx^2+my^2), u = a1*grad_x
//   sV [m/2] = (v0,  v1)               v = a1*grad_y
// ---------------------------------------------------------------------------
__global__ void __launch_bounds__(256, 2) fused_kernel(
    const float* __restrict__ pred,
    const float* __restrict__ target,
    const float* __restrict__ mask,
    const float* __restrict__ grad_x,
    const float* __restrict__ grad_y,
    const float* __restrict__ offset)
{
    __shared__ float4 sXY[M_PTS / 2];
    __shared__ float4 sPU[M_PTS / 2];
    __shared__ float2 sV [M_PTS / 2];
    __shared__ float  sWarp[8];

    const int i   = blockIdx.x;
    const int tid = threadIdx.x;
    const int base = i * M_PTS;

    // ---- per-box scalars (uniform within block) ----
    const float off0 = offset[2 * i], off1 = offset[2 * i + 1];
    const float px = pred[5 * i]     - off0;
    const float py = pred[5 * i + 1] - off1;
    const float pw = pred[5 * i + 2];
    const float ph = pred[5 * i + 3];
    const float pa = pred[5 * i + 4];
    const float gx = target[5 * i]     - off0;
    const float gy = target[5 * i + 1] - off1;
    const float gw = target[5 * i + 2];
    const float gh = target[5 * i + 3];
    const float ga = target[5 * i + 4];

    float cga, sga;  sincosf(ga, &sga, &cga);
    float cpa, spa;  sincosf(pa, &spa, &cpa);
    const float inv_gw = 1.0f / gw;
    const float inv_gh = 1.0f / gh;

    // ---- phase 1: prep m = tid, tid + 256 ----
    float jGx[2], jGy[2], jgx[2], jgy[2];

#pragma unroll
    for (int h = 0; h < 2; ++h) {
        const int m   = tid + h * 256;
        const int idx = base + m;

        const float2 mm = ((const float2*)mask)[idx];
        const float mx = mm.x, my = mm.y;

        const float dx = mx - gx, dy = my - gy;
        const float d  = sqrtf(dx * dx + dy * dy);
        float arg = -dx / d;
        arg = fminf(1.0f, fmaxf(-1.0f, arg));
        const float acosv = acosf(arg);
        const float s   = (gy >= my) ? 1.0f : -1.0f;
        const float beta = fmaf(s, acosv, ga);

        // cos/sin(ga +/- acosv) via identity (ct = arg, st = sqrt(1-arg^2))
        const float st = sqrtf(fmaxf(0.0f, 1.0f - arg * arg));
        const float cb = cga * arg - s * (sga * st);
        const float sb = sga * arg + s * (cga * st);

        const float d_w = fabsf(d * cb);
        const float d_h = fabsf(d * sb);

        // (1 - sigmoid(x)) = 1 / (1 + exp(x)),  exp via ex2
        const float e1 = ex2s(L2E * 15.0f * (d_w - gw) * inv_gw);
        const float e2 = ex2s(L2E * 15.0f * (d_h - gh) * inv_gh);
        const float a1 = 1.0f / ((1.0f + e1) * (1.0f + e2));

        const float dwp = pw * d_w * inv_gw;
        const float dhp = ph * d_h * inv_gh;
        const float wx =  dwp * cpa, wy = dwp * spa;
        const float hx = -dhp * spa, hy = dhp * cpa;

        const float HPI = 1.57079632679489662f;
        const float PI_ = 3.14159265358979323846f;
        float gpx, gpy;
        if (beta > -HPI && beta <= 0.0f) {          // q2 -> pts[2],[3]
            gpx =  wx - hx;  gpy =  wy - hy;
        } else if (beta > -PI_ && beta <= -HPI) {   // q3 -> pts[4],[5]
            gpx =  wx + hx;  gpy =  wy + hy;
        } else if (beta > HPI && beta <= PI_) {     // q4 -> pts[6],[7]
            gpx = -wx + hx;  gpy = -wy + hy;
        } else {                                    // else -> pts[0],[1]
            gpx = -wx - hx;  gpy = -wy - hy;
        }

        const float Gx = px + gpx;
        const float Gy = py + gpy;
        const float gxv = grad_x[idx];
        const float gyv = grad_y[idx];

        // k-side packed smem
        float* fXY = (float*)&sXY[m >> 1];
        float* fPU = (float*)&sPU[m >> 1];
        float* fV  = (float*)&sV [m >> 1];
        const int o = m & 1;
        fXY[o]     = mx;
        fXY[2 + o] = my;
        fPU[o]     = C2 * (mx * mx + my * my);
        fPU[2 + o] = a1 * gxv;
        fV[o]      = a1 * gyv;

        // j-side registers
        jGx[h] = Gx; jGy[h] = Gy; jgx[h] = gxv; jgy[h] = gyv;
    }
    __syncthreads();

    // ---- phase 2: core loop, f32x2 packed, 2 j per thread ----
    const ull na0 = pk(-2.0f * C2 * jGx[0], -2.0f * C2 * jGx[0]);
    const ull nb0 = pk(-2.0f * C2 * jGy[0], -2.0f * C2 * jGy[0]);
    const float Q0 = C2 * (jGx[0] * jGx[0] + jGy[0] * jGy[0]);
    const ull Q02 = pk(Q0, Q0);
    const ull na1 = pk(-2.0f * C2 * jGx[1], -2.0f * C2 * jGx[1]);
    const ull nb1 = pk(-2.0f * C2 * jGy[1], -2.0f * C2 * jGy[1]);
    const float Q1 = C2 * (jGx[1] * jGx[1] + jGy[1] * jGy[1]);
    const ull Q12 = pk(Q1, Q1);

    ull A0 = 0, B0 = 0, A1 = 0, B1 = 0;

    const ulonglong2* pXY = (const ulonglong2*)sXY;
    const ulonglong2* pPU = (const ulonglong2*)sPU;
    const ull*        pV  = (const ull*)sV;

#pragma unroll 4
    for (int k2 = 0; k2 < M_PTS / 2; ++k2) {
        const ulonglong2 xy = pXY[k2];   // .x = (mx0,mx1), .y = (my0,my1)
        const ulonglong2 pu = pPU[k2];   // .x = (P0,P1),   .y = (u0,u1)
        const ull        v2 = pV[k2];    //      (v0,v1)

        ull t0 = fma2(na0, xy.x, pu.x);
        t0 = fma2(nb0, xy.y, t0);
        t0 = add2(t0, Q02);
        const ull e0 = ex2p(t0);
        A0 = fma2(e0, pu.y, A0);
        B0 = fma2(e0, v2,   B0);

        ull t1 = fma2(na1, xy.x, pu.x);
        t1 = fma2(nb1, xy.y, t1);
        t1 = add2(t1, Q12);
        const ull e1 = ex2p(t1);
        A1 = fma2(e1, pu.y, A1);
        B1 = fma2(e1, v2,   B1);
    }

    // horizontal + j-weights
    float a0l, a0h, b0l, b0h, a1l, a1h, b1l, b1h;
    upk(a0l, a0h, A0); upk(b0l, b0h, B0);
    upk(a1l, a1h, A1); upk(b1l, b1h, B1);
    float partial = jgx[0] * (a0l + a0h) + jgy[0] * (b0l + b0h)
                  + jgx[1] * (a1l + a1h) + jgy[1] * (b1l + b1h);

    // deterministic block reduction
#pragma unroll
    for (int o = 16; o > 0; o >>= 1)
        partial += __shfl_down_sync(0xffffffffu, partial, o);
    if ((tid & 31) == 0) sWarp[tid >> 5] = partial;
    __syncthreads();
    if (tid < 8) {
        float v = sWarp[tid];
#pragma unroll
        for (int o = 4; o > 0; o >>= 1)
            v += __shfl_down_sync(0xffu, v, o);
        if (tid == 0) g_partials[i] = v;
    }
}

// ---------------------------------------------------------------------------
// Final reduce over 256 per-box partials + global scale.
// scale = LOSS_WEIGHT / (N * M * M * 2*pi*THETA2)
// ---------------------------------------------------------------------------
__global__ void __launch_bounds__(256) reduce_kernel(float* __restrict__ out)
{
    __shared__ float sWarp[8];
    const int tid = threadIdx.x;
    float s = g_partials[tid];
#pragma unroll
    for (int o = 16; o > 0; o >>= 1)
        s += __shfl_down_sync(0xffffffffu, s, o);
    if ((tid & 31) == 0) sWarp[tid >> 5] = s;
    __syncthreads();
    if (tid < 8) {
        float v = sWarp[tid];
#pragma unroll
        for (int o = 4; o > 0; o >>= 1)
            v += __shfl_down_sync(0xffu, v, o);
        if (tid == 0) {
            const double scale = 1.0 / ((double)N_BOX * (double)M_PTS * (double)M_PTS *
                                        2.0 * 3.14159265358979323846 * 400.0);
            *out = (float)((double)v * scale);
        }
    }
}

// ---------------------------------------------------------------------------
extern "C" void kernel_launch(void* const* d_in, const int* in_sizes, int n_in,
                              void* d_out, int out_size)
{
    const float* pred    = (const float*)d_in[0];
    const float* target  = (const float*)d_in[1];
    const float* mask    = (const float*)d_in[2];
    const float* grad_x  = (const float*)d_in[3];
    const float* grad_y  = (const float*)d_in[4];
    const float* offset  = (const float*)d_in[5];
    float* out = (float*)d_out;

    fused_kernel<<<N_BOX, 256>>>(pred, target, mask, grad_x, grad_y, offset);
    reduce_kernel<<<1, 256>>>(out);
}

// round 3
// speedup vs baseline: 1.1926x; 1.0072x over previous
#include <cuda_runtime.h>
#include <math.h>

#define N_BOX 256
#define M_PTS 512
#define NBLK  (N_BOX * 4)       // main-kernel blocks: 4 j-chunks of 128 per box

// c2 = log2(e) / (2 * THETA2^2), THETA2 = 400
#define C2  (1.44269504088896340736f / 320000.0f)
#define L2E 1.44269504088896340736f

// Scratch (device globals; no allocations allowed)
__device__ float4 g_XY[N_BOX * M_PTS / 2]; // per (i,k-pair): mx0,mx1,my0,my1
__device__ float4 g_PU[N_BOX * M_PTS / 2]; // per (i,k-pair): P0,P1,u0,u1
__device__ float2 g_V [N_BOX * M_PTS / 2]; // per (i,k-pair): v0,v1
__device__ float4 g_JD[N_BOX * M_PTS];     // per (i,j): Gx,Gy,grad_x,grad_y
__device__ float  g_partials[NBLK];
__device__ unsigned int g_count;

typedef unsigned long long ull;

__device__ __forceinline__ ull pk(float lo, float hi) {
    ull r; asm("mov.b64 %0, {%1, %2};" : "=l"(r) : "f"(lo), "f"(hi)); return r;
}
__device__ __forceinline__ void upk(float& lo, float& hi, ull v) {
    asm("mov.b64 {%0, %1}, %2;" : "=f"(lo), "=f"(hi) : "l"(v));
}
__device__ __forceinline__ ull fma2(ull a, ull b, ull c) {
    ull d; asm("fma.rn.f32x2 %0, %1, %2, %3;" : "=l"(d) : "l"(a), "l"(b), "l"(c)); return d;
}
__device__ __forceinline__ ull add2(ull a, ull b) {
    ull d; asm("add.rn.f32x2 %0, %1, %2;" : "=l"(d) : "l"(a), "l"(b)); return d;
}
__device__ __forceinline__ ull ex2p(ull t) {
    ull e;
    asm("{ .reg .f32 lo, hi, el, eh;\n\t"
        "  mov.b64 {lo, hi}, %1;\n\t"
        "  ex2.approx.f32 el, lo;\n\t"
        "  ex2.approx.f32 eh, hi;\n\t"
        "  mov.b64 %0, {el, eh}; }"
        : "=l"(e) : "l"(t));
    return e;
}
__device__ __forceinline__ float ex2s(float x) {
    float y; asm("ex2.approx.f32 %0, %1;" : "=f"(y) : "f"(x)); return y;
}

// ---------------------------------------------------------------------------
// Prep: one thread per (box i, point m). Writes pair-packed k-side arrays and
// the j-side float4. Also resets the completion counter for this replay.
// ---------------------------------------------------------------------------
__global__ void __launch_bounds__(512) prep_kernel(
    const float* __restrict__ pred,
    const float* __restrict__ target,
    const float* __restrict__ mask,
    const float* __restrict__ grad_x,
    const float* __restrict__ grad_y,
    const float* __restrict__ offset)
{
    const int i = blockIdx.x;
    const int m = threadIdx.x;
    const int idx = i * M_PTS + m;

    if (i == 0 && m == 0) g_count = 0u;   // reset for this graph replay

    const float off0 = offset[2 * i], off1 = offset[2 * i + 1];
    const float px = pred[5 * i]     - off0;
    const float py = pred[5 * i + 1] - off1;
    const float pw = pred[5 * i + 2];
    const float ph = pred[5 * i + 3];
    const float pa = pred[5 * i + 4];
    const float gx = target[5 * i]     - off0;
    const float gy = target[5 * i + 1] - off1;
    const float gw = target[5 * i + 2];
    const float gh = target[5 * i + 3];
    const float ga = target[5 * i + 4];

    float cga, sga;  sincosf(ga, &sga, &cga);
    float cpa, spa;  sincosf(pa, &spa, &cpa);
    const float inv_gw = 1.0f / gw;
    const float inv_gh = 1.0f / gh;

    const float2 mm = ((const float2*)mask)[idx];
    const float mx = mm.x, my = mm.y;

    const float dx = mx - gx, dy = my - gy;
    const float d  = sqrtf(dx * dx + dy * dy);
    float arg = -dx / d;
    arg = fminf(1.0f, fmaxf(-1.0f, arg));
    const float acosv = acosf(arg);
    const float s    = (gy >= my) ? 1.0f : -1.0f;
    const float beta = fmaf(s, acosv, ga);

    // cos/sin(ga +/- acosv) via identity (cos(acosv)=arg, sin(acosv)=st)
    const float st = sqrtf(fmaxf(0.0f, 1.0f - arg * arg));
    const float cb = cga * arg - s * (sga * st);
    const float sb = sga * arg + s * (cga * st);

    const float d_w = fabsf(d * cb);
    const float d_h = fabsf(d * sb);

    // (1 - sigmoid(x)) = 1 / (1 + exp(x)), exp via ex2
    const float e1 = ex2s(L2E * 15.0f * (d_w - gw) * inv_gw);
    const float e2 = ex2s(L2E * 15.0f * (d_h - gh) * inv_gh);
    const float a1 = 1.0f / ((1.0f + e1) * (1.0f + e2));

    const float dwp = pw * d_w * inv_gw;
    const float dhp = ph * d_h * inv_gh;
    const float wx =  dwp * cpa, wy = dwp * spa;
    const float hx = -dhp * spa, hy = dhp * cpa;

    const float HPI = 1.57079632679489662f;
    const float PI_ = 3.14159265358979323846f;
    float gpx, gpy;
    if (beta > -HPI && beta <= 0.0f) {          // q2 -> pts[2],[3]
        gpx =  wx - hx;  gpy =  wy - hy;
    } else if (beta > -PI_ && beta <= -HPI) {   // q3 -> pts[4],[5]
        gpx =  wx + hx;  gpy =  wy + hy;
    } else if (beta > HPI && beta <= PI_) {     // q4 -> pts[6],[7]
        gpx = -wx + hx;  gpy = -wy + hy;
    } else {                                    // else -> pts[0],[1]
        gpx = -wx - hx;  gpy = -wy - hy;
    }

    const float gxv = grad_x[idx];
    const float gyv = grad_y[idx];

    const int k2 = (i * M_PTS + m) >> 1;
    const int o  = m & 1;
    ((float*)&g_XY[k2])[o]     = mx;
    ((float*)&g_XY[k2])[2 + o] = my;
    ((float*)&g_PU[k2])[o]     = C2 * (mx * mx + my * my);
    ((float*)&g_PU[k2])[2 + o] = a1 * gxv;
    ((float*)&g_V [k2])[o]     = a1 * gyv;

    g_JD[idx] = make_float4(px + gpx, py + gpy, gxv, gyv);
}

// ---------------------------------------------------------------------------
// Main: 1024 blocks x 128 threads. Block = (box i, j-chunk of 128).
// Each thread owns one j, loops over 256 k-pairs with f32x2-packed math.
// Last block performs the deterministic final reduction and writes the output.
// ---------------------------------------------------------------------------
__global__ void __launch_bounds__(128, 8) main_kernel(float* __restrict__ out)
{
    __shared__ float4 sXY[M_PTS / 2];
    __shared__ float4 sPU[M_PTS / 2];
    __shared__ float2 sV [M_PTS / 2];
    __shared__ float  sWarp[4];
    __shared__ int    sLast;

    const int b   = blockIdx.x;
    const int i   = b >> 2;
    const int jc  = b & 3;
    const int tid = threadIdx.x;
    const int kbase = i * (M_PTS / 2);

    // stage this box's k-data (2 entries per thread per array)
#pragma unroll
    for (int r = 0; r < 2; ++r) {
        const int k2 = tid + r * 128;
        sXY[k2] = g_XY[kbase + k2];
        sPU[k2] = g_PU[kbase + k2];
        sV [k2] = g_V [kbase + k2];
    }
    __syncthreads();

    const int j = jc * 128 + tid;
    const float4 jd = g_JD[i * M_PTS + j];
    const ull na = pk(-2.0f * C2 * jd.x, -2.0f * C2 * jd.x);
    const ull nb = pk(-2.0f * C2 * jd.y, -2.0f * C2 * jd.y);
    const float Q = C2 * (jd.x * jd.x + jd.y * jd.y);
    const ull Q2 = pk(Q, Q);

    ull A = 0, B = 0;
    const ulonglong2* pXY = (const ulonglong2*)sXY;
    const ulonglong2* pPU = (const ulonglong2*)sPU;
    const ull*        pV  = (const ull*)sV;

#pragma unroll 8
    for (int k2 = 0; k2 < M_PTS / 2; ++k2) {
        const ulonglong2 xy = pXY[k2];   // (mx0,mx1) , (my0,my1)
        const ulonglong2 pu = pPU[k2];   // (P0,P1)   , (u0,u1)
        const ull        v2 = pV[k2];    // (v0,v1)

        ull t = fma2(na, xy.x, pu.x);
        t = fma2(nb, xy.y, t);
        t = add2(t, Q2);
        const ull e = ex2p(t);
        A = fma2(e, pu.y, A);
        B = fma2(e, v2,   B);
    }

    float al, ah, bl, bh;
    upk(al, ah, A); upk(bl, bh, B);
    float partial = jd.z * (al + ah) + jd.w * (bl + bh);

    // deterministic block reduction (4 warps)
#pragma unroll
    for (int o = 16; o > 0; o >>= 1)
        partial += __shfl_down_sync(0xffffffffu, partial, o);
    if ((tid & 31) == 0) sWarp[tid >> 5] = partial;
    __syncthreads();

    if (tid == 0) {
        float v = sWarp[0] + sWarp[1] + sWarp[2] + sWarp[3];
        g_partials[b] = v;
        __threadfence();
        unsigned int old = atomicAdd(&g_count, 1u);
        sLast = (old == NBLK - 1) ? 1 : 0;
    }
    __syncthreads();

    // last block: fixed-order final reduction (deterministic regardless of
    // which block executes it)
    if (sLast) {
        float s = 0.0f;
#pragma unroll
        for (int r = 0; r < NBLK / 128; ++r)
            s += __ldcg(&g_partials[tid + r * 128]);
#pragma unroll
        for (int o = 16; o > 0; o >>= 1)
            s += __shfl_down_sync(0xffffffffu, s, o);
        if ((tid & 31) == 0) sWarp[tid >> 5] = s;
        __syncthreads();
        if (tid == 0) {
            float v = sWarp[0] + sWarp[1] + sWarp[2] + sWarp[3];
            const double scale = 1.0 / ((double)N_BOX * (double)M_PTS * (double)M_PTS *
                                        2.0 * 3.14159265358979323846 * 400.0);
            *out = (float)((double)v * scale);
        }
    }
}

// ---------------------------------------------------------------------------
extern "C" void kernel_launch(void* const* d_in, const int* in_sizes, int n_in,
                              void* d_out, int out_size)
{
    const float* pred    = (const float*)d_in[0];
    const float* target  = (const float*)d_in[1];
    const float* mask    = (const float*)d_in[2];
    const float* grad_x  = (const float*)d_in[3];
    const float* grad_y  = (const float*)d_in[4];
    const float* offset  = (const float*)d_in[5];
    float* out = (float*)d_out;

    prep_kernel<<<N_BOX, 512>>>(pred, target, mask, grad_x, grad_y, offset);
    main_kernel<<<NBLK, 128>>>(out);
}

// round 4
// speedup vs baseline: 1.1938x; 1.0010x over previous
#include <cuda_runtime.h>
#include <math.h>

#define N_BOX 256
#define M_PTS 512
#define KPAIR (M_PTS / 2)        // 256 k-pairs per box
#define KHALF (KPAIR / 2)        // 128 k-pairs per block (k-split 2)
#define NBLK  (N_BOX * 4 * 2)    // 2048: boxes x 4 j-chunks x 2 k-halves

// c2 = log2(e) / (2 * THETA2^2), THETA2 = 400
#define C2  (1.44269504088896340736f / 320000.0f)
#define L2E 1.44269504088896340736f

// Scratch (device globals; no allocations allowed)
__device__ float4 g_XY[N_BOX * KPAIR]; // per (i,k-pair): mx0,mx1,my0,my1
__device__ float4 g_PU[N_BOX * KPAIR]; // per (i,k-pair): P0,P1,u0,u1
__device__ float2 g_V [N_BOX * KPAIR]; // per (i,k-pair): v0,v1
__device__ float4 g_JD[N_BOX * M_PTS]; // per (i,j): Gx,Gy,grad_x,grad_y
__device__ float  g_partials[NBLK];
__device__ unsigned int g_count = 0u;

typedef unsigned long long ull;

__device__ __forceinline__ ull pk(float lo, float hi) {
    ull r; asm("mov.b64 %0, {%1, %2};" : "=l"(r) : "f"(lo), "f"(hi)); return r;
}
__device__ __forceinline__ void upk(float& lo, float& hi, ull v) {
    asm("mov.b64 {%0, %1}, %2;" : "=f"(lo), "=f"(hi) : "l"(v));
}
__device__ __forceinline__ ull fma2(ull a, ull b, ull c) {
    ull d; asm("fma.rn.f32x2 %0, %1, %2, %3;" : "=l"(d) : "l"(a), "l"(b), "l"(c)); return d;
}
__device__ __forceinline__ ull ex2p(ull t) {
    ull e;
    asm("{ .reg .f32 lo, hi, el, eh;\n\t"
        "  mov.b64 {lo, hi}, %1;\n\t"
        "  ex2.approx.f32 el, lo;\n\t"
        "  ex2.approx.f32 eh, hi;\n\t"
        "  mov.b64 %0, {el, eh}; }"
        : "=l"(e) : "l"(t));
    return e;
}
__device__ __forceinline__ float ex2s(float x) {
    float y; asm("ex2.approx.f32 %0, %1;" : "=f"(y) : "f"(x)); return y;
}

// ---------------------------------------------------------------------------
// Prep: one thread per (box i, point m). No acosf / sincos-of-beta: quadrant
// selection and cos/sin(beta) derived from arg = cos(acosv) via identities,
// comparing arg against per-box cos/sin(ga) (cos is strictly decreasing on
// [0,pi], so beta-threshold tests map exactly to arg tests).
// ---------------------------------------------------------------------------
__global__ void __launch_bounds__(512) prep_kernel(
    const float* __restrict__ pred,
    const float* __restrict__ target,
    const float* __restrict__ mask,
    const float* __restrict__ grad_x,
    const float* __restrict__ grad_y,
    const float* __restrict__ offset)
{
    const int i = blockIdx.x;
    const int m = threadIdx.x;
    const int idx = i * M_PTS + m;

    if (i == 0 && m == 0) g_count = 0u;   // reset for this graph replay

    const float off0 = offset[2 * i], off1 = offset[2 * i + 1];
    const float px = pred[5 * i]     - off0;
    const float py = pred[5 * i + 1] - off1;
    const float pw = pred[5 * i + 2];
    const float ph = pred[5 * i + 3];
    const float pa = pred[5 * i + 4];
    const float gx = target[5 * i]     - off0;
    const float gy = target[5 * i + 1] - off1;
    const float gw = target[5 * i + 2];
    const float gh = target[5 * i + 3];
    const float ga = target[5 * i + 4];

    float cga, sga;  sincosf(ga, &sga, &cga);
    float cpa, spa;  sincosf(pa, &spa, &cpa);
    const float inv_gw = 1.0f / gw;
    const float inv_gh = 1.0f / gh;

    const float2 mm = ((const float2*)mask)[idx];
    const float mx = mm.x, my = mm.y;

    const float dx = mx - gx, dy = my - gy;
    const float r2  = dx * dx + dy * dy;
    const float rin = rsqrtf(fmaxf(r2, 1e-30f));
    const float d   = r2 * rin;
    float arg = -dx * rin;                       // cos(acosv)
    arg = fminf(1.0f, fmaxf(-1.0f, arg));
    const float st = fabsf(dy) * rin;            // sin(acosv) = |dy|/d
    const bool  spos = (gy >= my);               // beta = ga + s*acosv
    const float s = spos ? 1.0f : -1.0f;

    const float cb = cga * arg - s * (sga * st); // cos(beta)
    const float sb = sga * arg + s * (cga * st); // sin(beta)

    const float d_w = fabsf(d * cb);
    const float d_h = fabsf(d * sb);

    // (1 - sigmoid(x)) = 1 / (1 + exp(x)), exp via ex2
    const float e1 = ex2s(L2E * 15.0f * (d_w - gw) * inv_gw);
    const float e2 = ex2s(L2E * 15.0f * (d_h - gh) * inv_gh);
    const float a1 = 1.0f / ((1.0f + e1) * (1.0f + e2));

    const float dwp = pw * d_w * inv_gw;
    const float dhp = ph * d_h * inv_gh;
    const float wx =  dwp * cpa, wy = dwp * spa;
    const float hx = -dhp * spa, hy = dhp * cpa;

    // quadrant of beta (= ga + s*acosv, ga in [-pi/4, pi/4), acosv in [0,pi])
    // via arg-space comparisons; cos strictly decreasing on [0,pi].
    bool q2, q3, q4;
    if (spos) {
        // beta in [ga, ga+pi]
        q2 = (ga <= 0.0f) && (arg >= cga);                        // beta <= 0
        q3 = false;
        q4 = (arg < sga) && ((ga <= 0.0f) || (arg >= -cga));      // pi/2 < beta <= pi
    } else {
        // beta in [ga-pi, ga]
        q2 = (arg > -sga) && ((ga <= 0.0f) || (arg <= cga));      // -pi/2 < beta <= 0
        q3 = (arg <= -sga) && ((ga >= 0.0f) || (arg > -cga));     // -pi < beta <= -pi/2
        q4 = false;
    }

    float gpx, gpy;
    if (q2)      { gpx =  wx - hx;  gpy =  wy - hy; }
    else if (q3) { gpx =  wx + hx;  gpy =  wy + hy; }
    else if (q4) { gpx = -wx + hx;  gpy = -wy + hy; }
    else         { gpx = -wx - hx;  gpy = -wy - hy; }

    const float gxv = grad_x[idx];
    const float gyv = grad_y[idx];

    const int k2 = idx >> 1;
    const int o  = m & 1;
    ((float*)&g_XY[k2])[o]     = mx;
    ((float*)&g_XY[k2])[2 + o] = my;
    ((float*)&g_PU[k2])[o]     = C2 * (mx * mx + my * my);   // P (Q folded out)
    ((float*)&g_PU[k2])[2 + o] = a1 * gxv;
    ((float*)&g_V [k2])[o]     = a1 * gyv;

    g_JD[idx] = make_float4(px + gpx, py + gpy, gxv, gyv);
}

// ---------------------------------------------------------------------------
// Main: 2048 blocks x 128 threads. Block = (box i, j-chunk of 128, k-half).
// Each thread owns one j, loops over 128 k-pairs with f32x2-packed math:
//   s = P_k - a_j*mx_k - b_j*my_k  (2 fma2);  e = 2^s (2 MUFU);
//   A += e*u ; B += e*v (2 fma2);  partial_j = (gx*A + gy*B) * 2^(Q_j)
// launch_bounds(128,14): 14 blocks/SM -> 14 warps/SMSP, single wave.
// ---------------------------------------------------------------------------
__global__ void __launch_bounds__(128, 14) main_kernel(float* __restrict__ out)
{
    __shared__ float4 sXY[KHALF];
    __shared__ float4 sPU[KHALF];
    __shared__ float2 sV [KHALF];
    __shared__ float  sWarp[4];
    __shared__ int    sLast;

    const int b   = blockIdx.x;
    const int i   = b >> 3;
    const int jc  = (b >> 1) & 3;
    const int kc  = b & 1;
    const int tid = threadIdx.x;
    const int kbase = i * KPAIR + kc * KHALF;

    sXY[tid] = g_XY[kbase + tid];
    sPU[tid] = g_PU[kbase + tid];
    sV [tid] = g_V [kbase + tid];
    __syncthreads();

    const int j = jc * 128 + tid;
    const float4 jd = g_JD[i * M_PTS + j];
    const float naf = -2.0f * C2 * jd.x;
    const float nbf = -2.0f * C2 * jd.y;
    const ull na = pk(naf, naf);
    const ull nb = pk(nbf, nbf);
    const float Q = C2 * (jd.x * jd.x + jd.y * jd.y);
    const float twoQ = ex2s(Q);

    ull A = 0, B = 0;
    const ulonglong2* pXY = (const ulonglong2*)sXY;
    const ulonglong2* pPU = (const ulonglong2*)sPU;
    const ull*        pV  = (const ull*)sV;

#pragma unroll 2
    for (int k2 = 0; k2 < KHALF; ++k2) {
        const ulonglong2 xy = pXY[k2];   // (mx0,mx1) , (my0,my1)
        const ulonglong2 pu = pPU[k2];   // (P0,P1)   , (u0,u1)
        const ull        v2 = pV[k2];    // (v0,v1)

        ull t = fma2(na, xy.x, pu.x);
        t = fma2(nb, xy.y, t);
        const ull e = ex2p(t);
        A = fma2(e, pu.y, A);
        B = fma2(e, v2,   B);
    }

    float al, ah, bl, bh;
    upk(al, ah, A); upk(bl, bh, B);
    float partial = (jd.z * (al + ah) + jd.w * (bl + bh)) * twoQ;

    // deterministic block reduction (4 warps)
#pragma unroll
    for (int o = 16; o > 0; o >>= 1)
        partial += __shfl_down_sync(0xffffffffu, partial, o);
    if ((tid & 31) == 0) sWarp[tid >> 5] = partial;
    __syncthreads();

    if (tid == 0) {
        g_partials[b] = sWarp[0] + sWarp[1] + sWarp[2] + sWarp[3];
        __threadfence();
        unsigned int old = atomicAdd(&g_count, 1u);
        sLast = (old == NBLK - 1) ? 1 : 0;
    }
    __syncthreads();

    // last block: fixed-order final reduction (deterministic regardless of
    // which block executes it)
    if (sLast) {
        float s = 0.0f;
#pragma unroll
        for (int r = 0; r < NBLK / 128; ++r)
            s += __ldcg(&g_partials[tid + r * 128]);
#pragma unroll
        for (int o = 16; o > 0; o >>= 1)
            s += __shfl_down_sync(0xffffffffu, s, o);
        if ((tid & 31) == 0) sWarp[tid >> 5] = s;
        __syncthreads();
        if (tid == 0) {
            float v = sWarp[0] + sWarp[1] + sWarp[2] + sWarp[3];
            const double scale = 1.0 / ((double)N_BOX * (double)M_PTS * (double)M_PTS *
                                        2.0 * 3.14159265358979323846 * 400.0);
            *out = (float)((double)v * scale);
        }
    }
}

// ---------------------------------------------------------------------------
extern "C" void kernel_launch(void* const* d_in, const int* in_sizes, int n_in,
                              void* d_out, int out_size)
{
    const float* pred    = (const float*)d_in[0];
    const float* target  = (const float*)d_in[1];
    const float* mask    = (const float*)d_in[2];
    const float* grad_x  = (const float*)d_in[3];
    const float* grad_y  = (const float*)d_in[4];
    const float* offset  = (const float*)d_in[5];
    float* out = (float*)d_out;

    prep_kernel<<<N_BOX, 512>>>(pred, target, mask, grad_x, grad_y, offset);
    main_kernel<<<NBLK, 128>>>(out);
}